// round 4
// baseline (speedup 1.0000x reference)
#include <cuda_runtime.h>

#define BDIM 4096
#define D 128
#define BM 32
#define BN 128
#define NTHREADS 256
#define EPSV 1e-8f

typedef unsigned long long u64t;

// packed fp32x2 fma: d = a*b + d (elementwise on the two packed floats)
__device__ __forceinline__ void fma2(u64t& d, u64t a, u64t b) {
    asm("fma.rn.f32x2 %0, %1, %2, %0;" : "+l"(d) : "l"(a), "l"(b));
}
__device__ __forceinline__ u64t bcast2(float v) {
    u64t r;
    asm("mov.b64 %0, {%1, %1};" : "=l"(r) : "f"(v));
    return r;
}
__device__ __forceinline__ float2 unpack2(u64t v) {
    float2 r;
    asm("mov.b64 {%0, %1}, %2;" : "=f"(r.x), "=f"(r.y) : "l"(v));
    return r;
}

// scratch for precomputed squared norms
__device__ float g_xsq[BDIM];
__device__ float g_ysq[2][BDIM];

__global__ void prep_norms(const float* __restrict__ x,
                           const float* __restrict__ yp,
                           const float* __restrict__ yn) {
    int r = blockIdx.x * blockDim.x + threadIdx.x;  // 0 .. 3*4096-1
    if (r >= 3 * BDIM) return;
    int which = r >> 12;
    int row = r & (BDIM - 1);
    const float* src;
    float* dst;
    if (which == 0)      { src = x;  dst = g_xsq;    }
    else if (which == 1) { src = yp; dst = g_ysq[0]; }
    else                 { src = yn; dst = g_ysq[1]; }
    const float4* p = (const float4*)(src + (size_t)row * D);
    float s = 0.f;
#pragma unroll
    for (int i = 0; i < D / 4; i++) {
        float4 v = p[i];
        s += v.x * v.x + v.y * v.y + v.z * v.z + v.w * v.w;
    }
    dst[row] = s;
}

// Fused drift-field kernel.
// Each block: 32 rows of x, loops over both fields (pos/neg) and all 32
// column tiles of 128 y-rows. Per tile: S = X Y^T (32x128), w = exp(-d2/2)
// (diag masked), warp-local row sums, and acc += W @ Y (32x128x128).
// All heavy math uses packed fma.rn.f32x2.
__global__ __launch_bounds__(NTHREADS, 1)
void drift_kernel(const float* __restrict__ x,
                  const float* __restrict__ yp,
                  const float* __restrict__ yn,
                  float* __restrict__ out) {
    extern __shared__ float sm[];
    float* Xs   = sm;                 // BM * D      (plain row-major)
    float* Ys   = Xs + BM * D;        // BN * D      (XOR-swizzled float4 chunks)
    float* Ws   = Ys + BN * D;        // BM * BN     (row-major)
    float* ysqs = Ws + BM * BN;       // BN
    float* xsqs = ysqs + BN;          // BM
    float* sAcc = xsqs + BM;          // 2 * BM

    const int tid  = threadIdx.x;
    const int lane = tid & 31;
    const int rowg = tid >> 5;        // warp id: owns rows 4*rowg .. 4*rowg+3
    const int base = blockIdx.x * BM;

    // load X tile (plain layout, broadcast-read later)
    {
        const float4* gx = (const float4*)(x + (size_t)base * D);
        float4* xs4 = (float4*)Xs;
#pragma unroll
        for (int i = 0; i < (BM * D / 4) / NTHREADS; i++) {
            int c = tid + NTHREADS * i;
            xs4[c] = gx[c];
        }
    }
    if (tid < BM) xsqs[tid] = g_xsq[base + tid];
    if (tid < 2 * BM) sAcc[tid] = 0.f;

    // acc2[f][rr][p]: packed output accumulator, p packs d-pair within the
    // thread's float4 output chunk (cols 4*lane .. 4*lane+3)
    u64t acc2[2][4][2];
#pragma unroll
    for (int f = 0; f < 2; f++)
#pragma unroll
        for (int rr = 0; rr < 4; rr++) {
            acc2[f][rr][0] = 0ull;
            acc2[f][rr][1] = 0ull;
        }

    __syncthreads();

#pragma unroll
    for (int f = 0; f < 2; f++) {
        const float* Y = f ? yn : yp;
        for (int jt = 0; jt < BDIM / BN; jt++) {
            __syncthreads();  // previous tile's A-matmul done with Ys/Ws

            // load Y tile with full 5-bit XOR swizzle on float4 chunks:
            // logical (j, chunk ck) -> phys chunk (ck ^ (j & 31)) within row j
            {
                const float4* gy = (const float4*)(Y + (size_t)jt * BN * D);
                float4* ys4 = (float4*)Ys;
#pragma unroll
                for (int i = 0; i < (BN * D / 4) / NTHREADS; i++) {
                    int c = tid + NTHREADS * i;      // 0..4095
                    int j = c >> 5;
                    int ck = c & 31;
                    ys4[(j << 5) | (ck ^ (j & 31))] = gy[c];
                }
            }
            if (tid < BN) ysqs[tid] = g_ysq[f][jt * BN + tid];
            __syncthreads();

            // ---- S = X Y^T : per-thread 4 rows x 4 cols (cols = lane + 32*cc)
            // S2 packs partial sums over even/odd k; horizontal add at the end.
            u64t S2[4][4];
#pragma unroll
            for (int rr = 0; rr < 4; rr++)
#pragma unroll
                for (int cc = 0; cc < 4; cc++) S2[rr][cc] = 0ull;

            const ulonglong2* xs2 = (const ulonglong2*)Xs;   // 16B chunk view
            const ulonglong2* ys2 = (const ulonglong2*)Ys;
#pragma unroll 4
            for (int kq = 0; kq < D / 4; kq++) {
                ulonglong2 a[4], b[4];
#pragma unroll
                for (int rr = 0; rr < 4; rr++)
                    a[rr] = xs2[((rowg * 4 + rr) << 5) + kq];   // broadcast
#pragma unroll
                for (int cc = 0; cc < 4; cc++) {
                    int j = lane + 32 * cc;
                    b[cc] = ys2[(j << 5) | (kq ^ lane)];        // conflict-free
                }
#pragma unroll
                for (int rr = 0; rr < 4; rr++)
#pragma unroll
                    for (int cc = 0; cc < 4; cc++) {
                        fma2(S2[rr][cc], a[rr].x, b[cc].x);
                        fma2(S2[rr][cc], a[rr].y, b[cc].y);
                    }
            }

            // ---- epilogue: w = exp(-d2/2), diag mask, warp row sums, store W
#pragma unroll
            for (int rr = 0; rr < 4; rr++) {
                int r = rowg * 4 + rr;
                int gi = base + r;
                float xq = xsqs[r];
                float part = 0.f;
#pragma unroll
                for (int cc = 0; cc < 4; cc++) {
                    int jl = lane + 32 * cc;
                    int gj = jt * BN + jl;
                    float2 sh = unpack2(S2[rr][cc]);
                    float Sv = sh.x + sh.y;
                    float d2 = fmaxf(xq + ysqs[jl] - 2.f * Sv, 0.f);
                    float w = (gi == gj) ? 0.f : __expf(-0.5f * d2);
                    part += w;
                    Ws[r * BN + jl] = w;
                }
                // warp-exclusive rows: butterfly reduce, lane 0 accumulates
#pragma unroll
                for (int off = 16; off > 0; off >>= 1)
                    part += __shfl_xor_sync(0xffffffffu, part, off);
                if (lane == 0) sAcc[f * BM + r] += part;
            }
            __syncthreads();

            // ---- acc += W @ Y : per-thread 4 rows x 4 cols (cols = 4*lane+cc)
#pragma unroll 4
            for (int j = 0; j < BN; j++) {
                ulonglong2 yv = ys2[(j << 5) | (lane ^ (j & 31))]; // conflict-free
#pragma unroll
                for (int rr = 0; rr < 4; rr++) {
                    u64t w2 = bcast2(Ws[(rowg * 4 + rr) * BN + j]); // broadcast
                    fma2(acc2[f][rr][0], w2, yv.x);
                    fma2(acc2[f][rr][1], w2, yv.y);
                }
            }
        }
    }

    __syncthreads();

    // ---- final combine:
    // v = x * (0.5*rn - rp) + A_pos/dp - 0.5*A_neg/dn, r = s/max(s,EPS)
    const float4* xs4 = (const float4*)Xs;
#pragma unroll
    for (int rr = 0; rr < 4; rr++) {
        int r = rowg * 4 + rr;
        int gi = base + r;
        float sp = sAcc[r];
        float sn = sAcc[BM + r];
        float dp = fmaxf(sp, EPSV);
        float dn = fmaxf(sn, EPSV);
        float cx = 0.5f * (sn / dn) - (sp / dp);
        float ip = 1.f / dp;
        float in2 = 0.5f / dn;
        float4 xv = xs4[(r << 5) + lane];
        float2 p0 = unpack2(acc2[0][rr][0]);
        float2 p1 = unpack2(acc2[0][rr][1]);
        float2 n0 = unpack2(acc2[1][rr][0]);
        float2 n1 = unpack2(acc2[1][rr][1]);
        float4 o;
        o.x = xv.x * cx + p0.x * ip - n0.x * in2;
        o.y = xv.y * cx + p0.y * ip - n0.y * in2;
        o.z = xv.z * cx + p1.x * ip - n1.x * in2;
        o.w = xv.w * cx + p1.y * ip - n1.y * in2;
        ((float4*)out)[(size_t)gi * (D / 4) + lane] = o;
    }
}

extern "C" void kernel_launch(void* const* d_in, const int* in_sizes, int n_in,
                              void* d_out, int out_size) {
    const float* x  = (const float*)d_in[0];
    const float* yp = (const float*)d_in[1];
    const float* yn = (const float*)d_in[2];
    float* out = (float*)d_out;

    const int smem_bytes =
        (BM * D + BN * D + BM * BN + BN + BM + 2 * BM) * (int)sizeof(float);
    cudaFuncSetAttribute(drift_kernel,
                         cudaFuncAttributeMaxDynamicSharedMemorySize,
                         smem_bytes);

    prep_norms<<<(3 * BDIM + 255) / 256, 256>>>(x, yp, yn);
    drift_kernel<<<BDIM / BM, NTHREADS, smem_bytes>>>(x, yp, yn, out);
}

// round 6
// speedup vs baseline: 1.0010x; 1.0010x over previous
#include <cuda_runtime.h>
#include <cstdint>

#define BDIM 4096
#define D 128
#define BM 32
#define BN 128
#define NT 256
#define EPSV 1e-8f
#define WPAD 36

typedef unsigned long long u64t;

__device__ __forceinline__ void fma2(u64t& d, u64t a, u64t b) {
    asm("fma.rn.f32x2 %0, %1, %2, %0;" : "+l"(d) : "l"(a), "l"(b));
}
__device__ __forceinline__ u64t bcast2(float v) {
    u64t r; asm("mov.b64 %0, {%1, %1};" : "=l"(r) : "f"(v)); return r;
}
__device__ __forceinline__ float2 unpack2(u64t v) {
    float2 r; asm("mov.b64 {%0, %1}, %2;" : "=f"(r.x), "=f"(r.y) : "l"(v)); return r;
}
__device__ __forceinline__ void cp_async16(uint32_t dst, const void* src) {
    asm volatile("cp.async.cg.shared.global [%0], [%1], 16;" :: "r"(dst), "l"(src));
}
__device__ __forceinline__ void cp_commit() {
    asm volatile("cp.async.commit_group;");
}
__device__ __forceinline__ void cp_wait0() {
    asm volatile("cp.async.wait_group 0;");
}

__device__ float g_xsq[BDIM];
__device__ float g_ysq[2][BDIM];

__global__ void prep_norms(const float* __restrict__ x,
                           const float* __restrict__ yp,
                           const float* __restrict__ yn) {
    int r = blockIdx.x * blockDim.x + threadIdx.x;
    if (r >= 3 * BDIM) return;
    int which = r >> 12;
    int row = r & (BDIM - 1);
    const float* src;
    float* dst;
    if (which == 0)      { src = x;  dst = g_xsq;    }
    else if (which == 1) { src = yp; dst = g_ysq[0]; }
    else                 { src = yn; dst = g_ysq[1]; }
    const float4* p = (const float4*)(src + (size_t)row * D);
    float s = 0.f;
#pragma unroll
    for (int i = 0; i < D / 4; i++) {
        float4 v = p[i];
        s += v.x * v.x + v.y * v.y + v.z * v.z + v.w * v.w;
    }
    dst[row] = s;
}

// smem layout (floats):
//  Xs   [BM*D]            = 4096
//  Ys   [2][BN*D]         = 32768   (double-buffered, XOR-swizzled float4 chunks)
//  WsT  [BN][WPAD]        = 4608    (transposed W: WsT[j][r], pad 36)
//  ysqs [2][BN]           = 256
//  xsqs [BM]              = 32
//  sAcc [2*BM]            = 64
#define OFF_XS   0
#define OFF_YS   (BM * D)
#define OFF_WST  (OFF_YS + 2 * BN * D)
#define OFF_YSQ  (OFF_WST + BN * WPAD)
#define OFF_XSQ  (OFF_YSQ + 2 * BN)
#define OFF_SACC (OFF_XSQ + BM)
#define SMEM_FLOATS (OFF_SACC + 2 * BM)

__global__ __launch_bounds__(NT, 1)
void drift_kernel(const float* __restrict__ x,
                  const float* __restrict__ yp,
                  const float* __restrict__ yn,
                  float* __restrict__ out) {
    extern __shared__ float sm[];
    float* Xs   = sm + OFF_XS;
    float* Ys   = sm + OFF_YS;
    float* WsT  = sm + OFF_WST;
    float* Ysq  = sm + OFF_YSQ;
    float* xsqs = sm + OFF_XSQ;
    float* sAcc = sm + OFF_SACC;

    const int tid  = threadIdx.x;
    const int lane = tid & 31;
    const int wrp  = tid >> 5;       // 0..7
    const int bh   = wrp & 1;        // column/d half selector
    const int rgrp = wrp >> 1;       // 0..3 -> rows 8*rgrp .. 8*rgrp+7
    const int c0   = lane + 32 * bh; // S cols {c0, c0+64}; A d-pair index c0
    const int r0   = rgrp * 8;
    const int base = blockIdx.x * BM;

    // ---- preamble: X tile, norms, init, prefetch tile (f=0, jt=0)
    {
        const float4* gx = (const float4*)(x + (size_t)base * D);
        float4* xs4 = (float4*)Xs;
#pragma unroll
        for (int i = 0; i < (BM * D / 4) / NT; i++) {
            int c = tid + NT * i;
            xs4[c] = gx[c];
        }
    }
    if (tid < BM) xsqs[tid] = g_xsq[base + tid];
    if (tid < 2 * BM) sAcc[tid] = 0.f;
    if (tid < BN) Ysq[tid] = g_ysq[0][tid];
    {
        uint32_t ybase = (uint32_t)__cvta_generic_to_shared(Ys);
        const float4* gy = (const float4*)yp;
#pragma unroll
        for (int i = 0; i < (BN * D / 4) / NT; i++) {
            int c = tid + NT * i;
            int j = c >> 5, ck = c & 31;
            cp_async16(ybase + ((((j << 5) | (ck ^ (j & 31)))) << 4), gy + c);
        }
        cp_commit();
    }

    // persistent accumulators: accp[f][q][dd] = {A[r0+2q][d], A[r0+2q+1][d]}
    // with d = 2*c0 + dd
    u64t accp[2][4][2];
#pragma unroll
    for (int f = 0; f < 2; f++)
#pragma unroll
        for (int q = 0; q < 4; q++) {
            accp[f][q][0] = 0ull;
            accp[f][q][1] = 0ull;
        }

#pragma unroll
    for (int f = 0; f < 2; f++) {
        for (int jt = 0; jt < BDIM / BN; jt++) {
            const int cur = jt & 1;
            const float* Ysc = Ys + cur * (BN * D);

            cp_wait0();            // current buffer's cp.async complete
            __syncthreads();       // prev A-matmul done; buffers/W consistent

            // prefetch next tile into the other buffer
            {
                const float* nsrc = nullptr;
                const float* nsq  = nullptr;
                if (jt + 1 < BDIM / BN) {
                    nsrc = (f ? yn : yp) + (size_t)(jt + 1) * BN * D;
                    nsq  = &g_ysq[f][(jt + 1) * BN];
                } else if (f == 0) {
                    nsrc = yn;
                    nsq  = &g_ysq[1][0];
                }
                if (nsrc) {
                    float* Ysn = Ys + (cur ^ 1) * (BN * D);
                    uint32_t ybase = (uint32_t)__cvta_generic_to_shared(Ysn);
                    const float4* gy = (const float4*)nsrc;
#pragma unroll
                    for (int i = 0; i < (BN * D / 4) / NT; i++) {
                        int c = tid + NT * i;
                        int j = c >> 5, ck = c & 31;
                        cp_async16(ybase + ((((j << 5) | (ck ^ (j & 31)))) << 4),
                                   gy + c);
                    }
                    cp_commit();
                    if (tid < BN) Ysq[(cur ^ 1) * BN + tid] = nsq[tid];
                }
            }

            // ---- S = X Y^T : 8 rows x 2 cols per thread, k packed in pairs
            u64t S2[8][2];
#pragma unroll
            for (int rr = 0; rr < 8; rr++) { S2[rr][0] = 0ull; S2[rr][1] = 0ull; }

            const ulonglong2* xs2 = (const ulonglong2*)Xs;
            const ulonglong2* ys2 = (const ulonglong2*)Ysc;
#pragma unroll 4
            for (int kq = 0; kq < D / 4; kq++) {
                ulonglong2 bv0 = ys2[(c0 << 5) | (kq ^ lane)];
                ulonglong2 bv1 = ys2[((c0 + 64) << 5) | (kq ^ lane)];
#pragma unroll
                for (int rr = 0; rr < 8; rr++) {
                    ulonglong2 av = xs2[((r0 + rr) << 5) + kq];  // broadcast
                    fma2(S2[rr][0], av.x, bv0.x);
                    fma2(S2[rr][0], av.y, bv0.y);
                    fma2(S2[rr][1], av.x, bv1.x);
                    fma2(S2[rr][1], av.y, bv1.y);
                }
            }

            // ---- epilogue: w = exp(-d2/2), diag mask, row sums, WsT stores
            float ysq0 = Ysq[cur * BN + c0];
            float ysq1 = Ysq[cur * BN + c0 + 64];
            float wv[8][2];
#pragma unroll
            for (int rr = 0; rr < 8; rr++) {
                int r = r0 + rr;
                int gi = base + r;
                float xq = xsqs[r];
                float2 s0 = unpack2(S2[rr][0]);
                float2 s1 = unpack2(S2[rr][1]);
                float Sv0 = s0.x + s0.y;
                float Sv1 = s1.x + s1.y;
                float d20 = fmaxf(xq + ysq0 - 2.f * Sv0, 0.f);
                float d21 = fmaxf(xq + ysq1 - 2.f * Sv1, 0.f);
                int gj0 = jt * BN + c0;
                int gj1 = gj0 + 64;
                wv[rr][0] = (gi == gj0) ? 0.f : __expf(-0.5f * d20);
                wv[rr][1] = (gi == gj1) ? 0.f : __expf(-0.5f * d21);
                float part = wv[rr][0] + wv[rr][1];
#pragma unroll
                for (int off = 16; off > 0; off >>= 1)
                    part += __shfl_xor_sync(0xffffffffu, part, off);
                if (lane == 0) atomicAdd(&sAcc[f * BM + r], part);
            }
            // transposed store: WsT[c][r], 4x STS.128 (rows packed by 4)
#pragma unroll
            for (int cc = 0; cc < 2; cc++) {
                int c = c0 + 64 * cc;
                float4 lo = make_float4(wv[0][cc], wv[1][cc], wv[2][cc], wv[3][cc]);
                float4 hi = make_float4(wv[4][cc], wv[5][cc], wv[6][cc], wv[7][cc]);
                *(float4*)&WsT[c * WPAD + r0]     = lo;
                *(float4*)&WsT[c * WPAD + r0 + 4] = hi;
            }
            __syncthreads();

            // ---- A += W @ Y : rows packed in pairs via WsT, d pair = c0
#pragma unroll 4
            for (int j = 0; j < BN; j++) {
                // y[j][2*c0], y[j][2*c0+1]
                int chunk = (j << 5) | ((c0 >> 1) ^ (j & 31));
                const float* yp8 = Ysc + chunk * 4 + (c0 & 1) * 2;
                float2 yf = *(const float2*)yp8;
                u64t y0 = bcast2(yf.x);
                u64t y1 = bcast2(yf.y);
                const float* wr = WsT + j * WPAD + r0;     // broadcast
                ulonglong2 wlo = *(const ulonglong2*)wr;       // {w0,w1},{w2,w3}
                ulonglong2 whi = *(const ulonglong2*)(wr + 4); // {w4,w5},{w6,w7}
                fma2(accp[f][0][0], wlo.x, y0);
                fma2(accp[f][0][1], wlo.x, y1);
                fma2(accp[f][1][0], wlo.y, y0);
                fma2(accp[f][1][1], wlo.y, y1);
                fma2(accp[f][2][0], whi.x, y0);
                fma2(accp[f][2][1], whi.x, y1);
                fma2(accp[f][3][0], whi.y, y0);
                fma2(accp[f][3][1], whi.y, y1);
            }
        }
    }

    __syncthreads();

    // ---- final combine: v = x*(0.5*rn - rp) + Ap/dp - 0.5*An/dn
#pragma unroll
    for (int q = 0; q < 4; q++) {
        float2 p0 = unpack2(accp[0][q][0]);  // {Ap[r0+2q][d0], Ap[r0+2q+1][d0]}
        float2 p1 = unpack2(accp[0][q][1]);
        float2 n0 = unpack2(accp[1][q][0]);
        float2 n1 = unpack2(accp[1][q][1]);
#pragma unroll
        for (int h = 0; h < 2; h++) {
            int r = r0 + 2 * q + h;
            int gi = base + r;
            float sp = sAcc[r];
            float sn = sAcc[BM + r];
            float dp = fmaxf(sp, EPSV);
            float dn = fmaxf(sn, EPSV);
            float cx = 0.5f * (sn / dn) - (sp / dp);
            float ip = 1.f / dp;
            float in2 = 0.5f / dn;
            float2 xv = *(const float2*)&Xs[r * D + 2 * c0];
            float ap0 = h ? p0.y : p0.x, ap1 = h ? p1.y : p1.x;
            float an0 = h ? n0.y : n0.x, an1 = h ? n1.y : n1.x;
            float2 o;
            o.x = xv.x * cx + ap0 * ip - an0 * in2;
            o.y = xv.y * cx + ap1 * ip - an1 * in2;
            *(float2*)&out[(size_t)gi * D + 2 * c0] = o;
        }
    }
}

extern "C" void kernel_launch(void* const* d_in, const int* in_sizes, int n_in,
                              void* d_out, int out_size) {
    const float* x  = (const float*)d_in[0];
    const float* yp = (const float*)d_in[1];
    const float* yn = (const float*)d_in[2];
    float* out = (float*)d_out;

    const int smem_bytes = SMEM_FLOATS * (int)sizeof(float);
    cudaFuncSetAttribute(drift_kernel,
                         cudaFuncAttributeMaxDynamicSharedMemorySize,
                         smem_bytes);

    prep_norms<<<(3 * BDIM + 255) / 256, 256>>>(x, yp, yn);
    drift_kernel<<<BDIM / BM, NT, smem_bytes>>>(x, yp, yn, out);
}

// round 12
// speedup vs baseline: 2.7086x; 2.7061x over previous
#include <cuda_runtime.h>
#include <cuda_bf16.h>
#include <cstdint>

#define EPSV 1e-8f
#define PS 272                 // smem row stride in bytes (136 bf16)

// ---------------- gmem scratch (device globals; no allocs allowed) ----------
__device__ float g_xsq[4096];
__device__ float g_ysq[2][4096];
__device__ __align__(16) __nv_bfloat16 g_xh[4096 * 128];
__device__ __align__(16) __nv_bfloat16 g_xl[4096 * 128];
__device__ __align__(16) __nv_bfloat16 g_yh[2][4096 * 128];
__device__ __align__(16) __nv_bfloat16 g_yl[2][4096 * 128];
__device__ float A_scr[4][4096 * 128];   // [f*2+strip][row][d]
__device__ float s_scr[4][4096];         // [f*2+strip][row]

// ---------------- helpers ----------------
__device__ __forceinline__ uint32_t su32(const void* p) {
    return (uint32_t)__cvta_generic_to_shared(p);
}
__device__ __forceinline__ void ldsm4(uint32_t* r, uint32_t a) {
    asm volatile("ldmatrix.sync.aligned.m8n8.x4.shared.b16 {%0,%1,%2,%3},[%4];"
                 : "=r"(r[0]), "=r"(r[1]), "=r"(r[2]), "=r"(r[3]) : "r"(a));
}
__device__ __forceinline__ void ldsm4t(uint32_t* r, uint32_t a) {
    asm volatile("ldmatrix.sync.aligned.m8n8.x4.trans.shared.b16 {%0,%1,%2,%3},[%4];"
                 : "=r"(r[0]), "=r"(r[1]), "=r"(r[2]), "=r"(r[3]) : "r"(a));
}
__device__ __forceinline__ void mma16816(float* c, const uint32_t* a,
                                         uint32_t b0, uint32_t b1) {
    asm volatile(
        "mma.sync.aligned.m16n8k16.row.col.f32.bf16.bf16.f32 "
        "{%0,%1,%2,%3},{%4,%5,%6,%7},{%8,%9},{%0,%1,%2,%3};"
        : "+f"(c[0]), "+f"(c[1]), "+f"(c[2]), "+f"(c[3])
        : "r"(a[0]), "r"(a[1]), "r"(a[2]), "r"(a[3]), "r"(b0), "r"(b1));
}
#define CP16(dst, src) \
    asm volatile("cp.async.cg.shared.global [%0],[%1],16;" :: "r"(dst), "l"(src))
#define CP_COMMIT() asm volatile("cp.async.commit_group;")
#define CP_WAIT1()  asm volatile("cp.async.wait_group 1;")
#define CP_WAIT0()  asm volatile("cp.async.wait_group 0;")

// pack (a,b) to bf16x2, return residuals
__device__ __forceinline__ uint32_t pk_hi(float a, float b, float& ra, float& rb) {
    __nv_bfloat162 h = __floats2bfloat162_rn(a, b);
    ra = a - __bfloat162float(__low2bfloat16(h));
    rb = b - __bfloat162float(__high2bfloat16(h));
    return *reinterpret_cast<uint32_t*>(&h);
}
__device__ __forceinline__ uint32_t pk(float a, float b) {
    __nv_bfloat162 h = __floats2bfloat162_rn(a, b);
    return *reinterpret_cast<uint32_t*>(&h);
}

// ---------------- prep: norms + bf16 hi/lo splits ----------------
__global__ void prep(const float* __restrict__ x,
                     const float* __restrict__ yp,
                     const float* __restrict__ yn) {
    int r = blockIdx.x * blockDim.x + threadIdx.x;
    if (r >= 3 * 4096) return;
    int which = r >> 12, row = r & 4095;
    const float* src;
    __nv_bfloat16 *dh, *dl;
    float* ds;
    if (which == 0)      { src = x;  dh = g_xh;    dl = g_xl;    ds = g_xsq;    }
    else if (which == 1) { src = yp; dh = g_yh[0]; dl = g_yl[0]; ds = g_ysq[0]; }
    else                 { src = yn; dh = g_yh[1]; dl = g_yl[1]; ds = g_ysq[1]; }
    const float4* p = (const float4*)(src + (size_t)row * 128);
    uint32_t* oh = (uint32_t*)(dh + (size_t)row * 128);
    uint32_t* ol = (uint32_t*)(dl + (size_t)row * 128);
    float s = 0.f;
#pragma unroll
    for (int i = 0; i < 32; i++) {
        float4 v = p[i];
        s += v.x * v.x + v.y * v.y + v.z * v.z + v.w * v.w;
        float r0, r1, r2, r3;
        oh[2 * i]     = pk_hi(v.x, v.y, r0, r1);
        oh[2 * i + 1] = pk_hi(v.z, v.w, r2, r3);
        ol[2 * i]     = pk(r0, r1);
        ol[2 * i + 1] = pk(r2, r3);
    }
    ds[row] = s;
}

// ---------------- smem layout (bytes) ----------------
#define SM_XH 0
#define SM_XL 17408
#define SM_Y  34816            // YH buf0; YL = +YTILE; buf stride YBUF
#define YTILE 34816
#define YBUF  69632
#define SM_WH (SM_Y + 2 * YBUF)        // 174080
#define SM_WL (SM_WH + 17408)          // 191488
#define SM_F  208896                   // floats: xsq[64] ysq[2][128] sAcc[2][64]
#define SMEM_TOTAL (SM_F + 1792)

__global__ __launch_bounds__(256, 1)
void drift_main() {
    extern __shared__ char sm[];
    const uint32_t base = su32(sm);
    float* xsqS = (float*)(sm + SM_F);   // [64]
    float* ysqS = xsqS + 64;             // [2][128]
    float* sAcc = ysqS + 256;            // [2][64]

    const int tid = threadIdx.x, lane = tid & 31, w = tid >> 5;
    const int wm = w >> 1, wn = w & 1;
    const int rb = blockIdx.x >> 1, strip = blockIdx.x & 1;
    const int e = lane & 7, q = lane >> 3, g = lane >> 2, tig = lane & 3;

    // per-lane ldmatrix base offsets
    const uint32_t aBase = (uint32_t)((wm * 16 + e + (q & 1) * 8) * PS + (q >> 1) * 16);
    const uint32_t bBase = (uint32_t)((wn * 64 + e + (q >> 1) * 8) * PS + (q & 1) * 16);
    const uint32_t tBase = (uint32_t)((e + (q & 1) * 8) * PS + (wn * 64 + (q >> 1) * 8) * 2);

    // ---- preload X tiles + Y tile 0 (one cp.async group)
    {
        const size_t xoff = (size_t)rb * 64 * 128;
        for (int i = tid; i < 64 * 16; i += 256) {
            int row = i >> 4, ch = i & 15;
            CP16(base + SM_XH + row * PS + ch * 16, g_xh + xoff + row * 128 + ch * 8);
            CP16(base + SM_XL + row * PS + ch * 16, g_xl + xoff + row * 128 + ch * 8);
        }
        const size_t yoff = (size_t)strip * 2048 * 128;
        for (int i = tid; i < 128 * 16; i += 256) {
            int row = i >> 4, ch = i & 15;
            CP16(base + SM_Y + row * PS + ch * 16, g_yh[0] + yoff + row * 128 + ch * 8);
            CP16(base + SM_Y + YTILE + row * PS + ch * 16,
                 g_yl[0] + yoff + row * 128 + ch * 8);
        }
        CP_COMMIT();
    }
    if (tid < 64)  xsqS[tid] = g_xsq[rb * 64 + tid];
    if (tid < 128) ysqS[tid] = g_ysq[0][strip * 2048 + tid];
    if (tid < 128) sAcc[tid] = 0.f;

    float accA[8][4];
#pragma unroll
    for (int nt = 0; nt < 8; nt++)
#pragma unroll
        for (int k = 0; k < 4; k++) accA[nt][k] = 0.f;

#pragma unroll 1
    for (int t = 0; t < 32; t++) {
        const int f = t >> 4, jt = t & 15, b = t & 1;
        const int jbase = strip * 2048 + jt * 128;

        __syncthreads();   // prev iteration's compute done (buf b^1 free)

        // prefetch next Y tile
        if (t + 1 < 32) {
            const int f2 = (t + 1) >> 4, j2 = (t + 1) & 15, nb = b ^ 1;
            const int jb2 = strip * 2048 + j2 * 128;
            const uint32_t yh = base + SM_Y + nb * YBUF, yl = yh + YTILE;
            const size_t yoff = (size_t)jb2 * 128;
            for (int i = tid; i < 128 * 16; i += 256) {
                int row = i >> 4, ch = i & 15;
                CP16(yh + row * PS + ch * 16, g_yh[f2] + yoff + row * 128 + ch * 8);
                CP16(yl + row * PS + ch * 16, g_yl[f2] + yoff + row * 128 + ch * 8);
            }
            CP_COMMIT();
            if (tid < 128) ysqS[nb * 128 + tid] = g_ysq[f2][jb2 + tid];
            CP_WAIT1();
        } else {
            CP_WAIT0();
        }
        __syncthreads();

        const uint32_t yh = base + SM_Y + b * YBUF, yl = yh + YTILE;

        // ---- GEMM1: S = Xh Yh^T + Xh Yl^T + Xl Yh^T
        float S[8][4];
#pragma unroll
        for (int nt = 0; nt < 8; nt++)
#pragma unroll
            for (int k = 0; k < 4; k++) S[nt][k] = 0.f;

#pragma unroll
        for (int ks = 0; ks < 8; ks++) {
            uint32_t axh[4], axl[4];
            ldsm4(axh, base + SM_XH + aBase + ks * 32);
            ldsm4(axl, base + SM_XL + aBase + ks * 32);
            uint32_t byh[4][4], byl[4][4];
#pragma unroll
            for (int p = 0; p < 4; p++) {
                ldsm4(byh[p], yh + bBase + p * 4352 + ks * 32);
                ldsm4(byl[p], yl + bBase + p * 4352 + ks * 32);
            }
#pragma unroll
            for (int nt = 0; nt < 8; nt++) {
                uint32_t* bh = &byh[nt >> 1][(nt & 1) * 2];
                uint32_t* bl = &byl[nt >> 1][(nt & 1) * 2];
                mma16816(S[nt], axh, bh[0], bh[1]);
                mma16816(S[nt], axh, bl[0], bl[1]);
                mma16816(S[nt], axl, bh[0], bh[1]);
            }
        }

        // ---- epilogue: w = exp(-d2/2), diag mask, row sums, W hi/lo to smem
        {
            const int rlo = rb * 64 + wm * 16 + g, rhi = rlo + 8;
            const float xqlo = xsqS[wm * 16 + g], xqhi = xsqS[wm * 16 + g + 8];
            const float* ys = ysqS + b * 128;
            float rslo = 0.f, rshi = 0.f;
#pragma unroll
            for (int nt = 0; nt < 8; nt++) {
                const int c0 = wn * 64 + nt * 8 + 2 * tig;
                const int gj0 = jbase + c0;
                const float yq0 = ys[c0], yq1 = ys[c0 + 1];
                float w00 = (rlo == gj0) ? 0.f
                    : __expf(-0.5f * fmaxf(xqlo + yq0 - 2.f * S[nt][0], 0.f));
                float w01 = (rlo == gj0 + 1) ? 0.f
                    : __expf(-0.5f * fmaxf(xqlo + yq1 - 2.f * S[nt][1], 0.f));
                float w10 = (rhi == gj0) ? 0.f
                    : __expf(-0.5f * fmaxf(xqhi + yq0 - 2.f * S[nt][2], 0.f));
                float w11 = (rhi == gj0 + 1) ? 0.f
                    : __expf(-0.5f * fmaxf(xqhi + yq1 - 2.f * S[nt][3], 0.f));
                rslo += w00 + w01;
                rshi += w10 + w11;
                float r0, r1, r2, r3;
                const int olo = (wm * 16 + g) * PS + c0 * 2;
                const int ohi = olo + 8 * PS;
                *(uint32_t*)(sm + SM_WH + olo) = pk_hi(w00, w01, r0, r1);
                *(uint32_t*)(sm + SM_WH + ohi) = pk_hi(w10, w11, r2, r3);
                *(uint32_t*)(sm + SM_WL + olo) = pk(r0, r1);
                *(uint32_t*)(sm + SM_WL + ohi) = pk(r2, r3);
            }
            rslo += __shfl_xor_sync(0xffffffffu, rslo, 1);
            rslo += __shfl_xor_sync(0xffffffffu, rslo, 2);
            rshi += __shfl_xor_sync(0xffffffffu, rshi, 1);
            rshi += __shfl_xor_sync(0xffffffffu, rshi, 2);
            if (tig == 0) {
                atomicAdd(&sAcc[f * 64 + wm * 16 + g], rslo);
                atomicAdd(&sAcc[f * 64 + wm * 16 + g + 8], rshi);
            }
        }
        __syncthreads();

        // ---- GEMM2: A += Wh Yh + Wh Yl + Wl Yh (B via ldmatrix.trans)
#pragma unroll
        for (int ks = 0; ks < 8; ks++) {
            uint32_t awh[4], awl[4];
            ldsm4(awh, base + SM_WH + aBase + ks * 32);
            ldsm4(awl, base + SM_WL + aBase + ks * 32);
            uint32_t tyh[4][4], tyl[4][4];
#pragma unroll
            for (int p = 0; p < 4; p++) {
                ldsm4t(tyh[p], yh + tBase + p * 32 + ks * 4352);
                ldsm4t(tyl[p], yl + tBase + p * 32 + ks * 4352);
            }
#pragma unroll
            for (int nt = 0; nt < 8; nt++) {
                uint32_t* bh = &tyh[nt >> 1][(nt & 1) * 2];
                uint32_t* bl = &tyl[nt >> 1][(nt & 1) * 2];
                mma16816(accA[nt], awh, bh[0], bh[1]);
                mma16816(accA[nt], awh, bl[0], bl[1]);
                mma16816(accA[nt], awl, bh[0], bh[1]);
            }
        }

        // ---- end of field: dump A partials, reset accumulators
        if (jt == 15) {
            const int rlo = rb * 64 + wm * 16 + g;
            float* dstB = A_scr[f * 2 + strip];
#pragma unroll
            for (int nt = 0; nt < 8; nt++) {
                const int c = wn * 64 + nt * 8 + 2 * tig;
                float* d0 = dstB + (size_t)rlo * 128 + c;
                d0[0] = accA[nt][0];
                d0[1] = accA[nt][1];
                d0[8 * 128] = accA[nt][2];
                d0[8 * 128 + 1] = accA[nt][3];
#pragma unroll
                for (int k = 0; k < 4; k++) accA[nt][k] = 0.f;
            }
        }
    }

    __syncthreads();
    if (tid < 128) {
        int f = tid >> 6, r = tid & 63;
        s_scr[f * 2 + strip][rb * 64 + r] = sAcc[tid];
    }
}

// ---------------- combine ----------------
__global__ void combine_k(const float* __restrict__ x, float* __restrict__ out) {
    const int i = blockIdx.x;      // 4096 rows
    const int d = threadIdx.x;     // 128 features
    float sp = s_scr[0][i] + s_scr[1][i];
    float sn = s_scr[2][i] + s_scr[3][i];
    float Ap = A_scr[0][(size_t)i * 128 + d] + A_scr[1][(size_t)i * 128 + d];
    float An = A_scr[2][(size_t)i * 128 + d] + A_scr[3][(size_t)i * 128 + d];
    float dp = fmaxf(sp, EPSV), dn = fmaxf(sn, EPSV);
    float cx = 0.5f * (sn / dn) - sp / dp;
    out[(size_t)i * 128 + d] = x[(size_t)i * 128 + d] * cx + Ap / dp - 0.5f * An / dn;
}

extern "C" void kernel_launch(void* const* d_in, const int* in_sizes, int n_in,
                              void* d_out, int out_size) {
    const float* x  = (const float*)d_in[0];
    const float* yp = (const float*)d_in[1];
    const float* yn = (const float*)d_in[2];
    float* out = (float*)d_out;

    cudaFuncSetAttribute(drift_main,
                         cudaFuncAttributeMaxDynamicSharedMemorySize, SMEM_TOTAL);

    prep<<<48, 256>>>(x, yp, yn);
    drift_main<<<128, 256, SMEM_TOTAL>>>();
    combine_k<<<4096, 128>>>(x, out);
}

// round 13
// speedup vs baseline: 4.6148x; 1.7037x over previous
#include <cuda_runtime.h>
#include <cuda_bf16.h>
#include <cstdint>

#define EPSV 1e-8f
#define PS 272                 // smem row stride in bytes (136 bf16)

// ---------------- gmem scratch (device globals; no allocs allowed) ----------
__device__ float g_xsq[4096];
__device__ float g_ysq[2][4096];
__device__ __align__(16) uint32_t g_xb[4096 * 64];      // bf16x2 packed
__device__ __align__(16) uint32_t g_yb[2][4096 * 64];
__device__ float A_scr[4][4096 * 128];   // [f*2+strip][row][d]
__device__ float s_scr[4][4096];         // [f*2+strip][row]

// ---------------- helpers ----------------
__device__ __forceinline__ uint32_t su32(const void* p) {
    return (uint32_t)__cvta_generic_to_shared(p);
}
__device__ __forceinline__ void ldsm4(uint32_t* r, uint32_t a) {
    asm volatile("ldmatrix.sync.aligned.m8n8.x4.shared.b16 {%0,%1,%2,%3},[%4];"
                 : "=r"(r[0]), "=r"(r[1]), "=r"(r[2]), "=r"(r[3]) : "r"(a));
}
__device__ __forceinline__ void ldsm4t(uint32_t* r, uint32_t a) {
    asm volatile("ldmatrix.sync.aligned.m8n8.x4.trans.shared.b16 {%0,%1,%2,%3},[%4];"
                 : "=r"(r[0]), "=r"(r[1]), "=r"(r[2]), "=r"(r[3]) : "r"(a));
}
__device__ __forceinline__ void mma16816(float* c, const uint32_t* a,
                                         uint32_t b0, uint32_t b1) {
    asm volatile(
        "mma.sync.aligned.m16n8k16.row.col.f32.bf16.bf16.f32 "
        "{%0,%1,%2,%3},{%4,%5,%6,%7},{%8,%9},{%0,%1,%2,%3};"
        : "+f"(c[0]), "+f"(c[1]), "+f"(c[2]), "+f"(c[3])
        : "r"(a[0]), "r"(a[1]), "r"(a[2]), "r"(a[3]), "r"(b0), "r"(b1));
}
#define CP16(dst, src) \
    asm volatile("cp.async.cg.shared.global [%0],[%1],16;" :: "r"(dst), "l"(src))
#define CP_COMMIT() asm volatile("cp.async.commit_group;")
#define CP_WAIT1()  asm volatile("cp.async.wait_group 1;")
#define CP_WAIT0()  asm volatile("cp.async.wait_group 0;")

__device__ __forceinline__ uint32_t pk(float a, float b) {
    __nv_bfloat162 h = __floats2bfloat162_rn(a, b);
    return *reinterpret_cast<uint32_t*>(&h);
}

// ---------------- prep: norms + bf16 pack, 8 threads per row --------------
__global__ void prep(const float* __restrict__ x,
                     const float* __restrict__ yp,
                     const float* __restrict__ yn) {
    int idx = blockIdx.x * blockDim.x + threadIdx.x;   // 0 .. 3*4096*8-1
    if (idx >= 3 * 4096 * 8) return;
    int seg = idx & 7;
    int r = idx >> 3;
    int which = r >> 12, row = r & 4095;
    const float* src;
    uint32_t* db;
    float* ds;
    if (which == 0)      { src = x;  db = g_xb;    ds = g_xsq;    }
    else if (which == 1) { src = yp; db = g_yb[0]; ds = g_ysq[0]; }
    else                 { src = yn; db = g_yb[1]; ds = g_ysq[1]; }
    const float4* p = (const float4*)(src + (size_t)row * 128 + seg * 16);
    uint32_t* ob = db + (size_t)row * 64 + seg * 8;
    float s = 0.f;
#pragma unroll
    for (int i = 0; i < 4; i++) {
        float4 v = p[i];
        s += v.x * v.x + v.y * v.y + v.z * v.z + v.w * v.w;
        ob[2 * i]     = pk(v.x, v.y);
        ob[2 * i + 1] = pk(v.z, v.w);
    }
    s += __shfl_xor_sync(0xffffffffu, s, 1);
    s += __shfl_xor_sync(0xffffffffu, s, 2);
    s += __shfl_xor_sync(0xffffffffu, s, 4);
    if (seg == 0) ds[row] = s;
}

// ---------------- smem layout (bytes) ----------------
#define SM_X  0                        // 64 x PS   = 17408
#define SM_Y  17408                    // 2 bufs x 128 x PS (stride YBUF)
#define YBUF  34816
#define SM_W  (SM_Y + 2 * YBUF)        // 87040, 64 x PS
#define SM_F  (SM_W + 17408)           // 104448: xsq[64] ysq[2][128] sAcc[2][64]
#define SMEM_TOTAL (SM_F + 1792)

__global__ __launch_bounds__(256, 1)
void drift_main() {
    extern __shared__ char sm[];
    const uint32_t base = su32(sm);
    float* xsqS = (float*)(sm + SM_F);   // [64]
    float* ysqS = xsqS + 64;             // [2][128]
    float* sAcc = ysqS + 256;            // [2][64]

    const int tid = threadIdx.x, lane = tid & 31, w = tid >> 5;
    const int wm = w >> 1, wn = w & 1;
    const int rb = blockIdx.x >> 1, strip = blockIdx.x & 1;
    const int e = lane & 7, q = lane >> 3, g = lane >> 2, tig = lane & 3;

    // per-lane ldmatrix base offsets
    const uint32_t aBase = (uint32_t)((wm * 16 + e + (q & 1) * 8) * PS + (q >> 1) * 16);
    const uint32_t bBase = (uint32_t)((wn * 64 + e + (q >> 1) * 8) * PS + (q & 1) * 16);
    const uint32_t tBase = (uint32_t)((e + (q & 1) * 8) * PS + (wn * 64 + (q >> 1) * 8) * 2);

    // ---- preload X tile + Y tile 0 (one cp.async group)
    {
        const size_t xoff = (size_t)rb * 64 * 64;         // uint32 units
        for (int i = tid; i < 64 * 16; i += 256) {
            int row = i >> 4, ch = i & 15;
            CP16(base + SM_X + row * PS + ch * 16, g_xb + xoff + row * 64 + ch * 4);
        }
        const size_t yoff = (size_t)strip * 2048 * 64;
        for (int i = tid; i < 128 * 16; i += 256) {
            int row = i >> 4, ch = i & 15;
            CP16(base + SM_Y + row * PS + ch * 16, g_yb[0] + yoff + row * 64 + ch * 4);
        }
        CP_COMMIT();
    }
    if (tid < 64)  xsqS[tid] = g_xsq[rb * 64 + tid];
    if (tid < 128) ysqS[tid] = g_ysq[0][strip * 2048 + tid];
    if (tid < 128) sAcc[tid] = 0.f;

    float accA[8][4];
#pragma unroll
    for (int nt = 0; nt < 8; nt++)
#pragma unroll
        for (int k = 0; k < 4; k++) accA[nt][k] = 0.f;

#pragma unroll 1
    for (int t = 0; t < 32; t++) {
        const int f = t >> 4, jt = t & 15, b = t & 1;
        const int jbase = strip * 2048 + jt * 128;

        __syncthreads();   // prev iteration's compute done (buf b^1 free)

        // prefetch next Y tile
        if (t + 1 < 32) {
            const int f2 = (t + 1) >> 4, j2 = (t + 1) & 15, nb = b ^ 1;
            const int jb2 = strip * 2048 + j2 * 128;
            const uint32_t yd = base + SM_Y + nb * YBUF;
            const size_t yoff = (size_t)jb2 * 64;
            for (int i = tid; i < 128 * 16; i += 256) {
                int row = i >> 4, ch = i & 15;
                CP16(yd + row * PS + ch * 16, g_yb[f2] + yoff + row * 64 + ch * 4);
            }
            CP_COMMIT();
            if (tid < 128) ysqS[nb * 128 + tid] = g_ysq[f2][jb2 + tid];
            CP_WAIT1();
        } else {
            CP_WAIT0();
        }
        __syncthreads();

        const uint32_t yb = base + SM_Y + b * YBUF;

        // ---- GEMM1: S = Xb Yb^T  (bf16 x bf16, fp32 accum)
        float S[8][4];
#pragma unroll
        for (int nt = 0; nt < 8; nt++)
#pragma unroll
            for (int k = 0; k < 4; k++) S[nt][k] = 0.f;

#pragma unroll
        for (int ks = 0; ks < 8; ks++) {
            uint32_t ax[4];
            ldsm4(ax, base + SM_X + aBase + ks * 32);
            uint32_t by[4][4];
#pragma unroll
            for (int p = 0; p < 4; p++)
                ldsm4(by[p], yb + bBase + p * 4352 + ks * 32);
#pragma unroll
            for (int nt = 0; nt < 8; nt++) {
                uint32_t* bh = &by[nt >> 1][(nt & 1) * 2];
                mma16816(S[nt], ax, bh[0], bh[1]);
            }
        }

        // ---- epilogue: w = exp(-d2/2), diag mask, row sums, W (bf16) to smem
        {
            const int rlo = rb * 64 + wm * 16 + g, rhi = rlo + 8;
            const float xqlo = xsqS[wm * 16 + g], xqhi = xsqS[wm * 16 + g + 8];
            const float* ys = ysqS + b * 128;
            float rslo = 0.f, rshi = 0.f;
#pragma unroll
            for (int nt = 0; nt < 8; nt++) {
                const int c0 = wn * 64 + nt * 8 + 2 * tig;
                const int gj0 = jbase + c0;
                const float yq0 = ys[c0], yq1 = ys[c0 + 1];
                float w00 = (rlo == gj0) ? 0.f
                    : __expf(-0.5f * fmaxf(xqlo + yq0 - 2.f * S[nt][0], 0.f));
                float w01 = (rlo == gj0 + 1) ? 0.f
                    : __expf(-0.5f * fmaxf(xqlo + yq1 - 2.f * S[nt][1], 0.f));
                float w10 = (rhi == gj0) ? 0.f
                    : __expf(-0.5f * fmaxf(xqhi + yq0 - 2.f * S[nt][2], 0.f));
                float w11 = (rhi == gj0 + 1) ? 0.f
                    : __expf(-0.5f * fmaxf(xqhi + yq1 - 2.f * S[nt][3], 0.f));
                rslo += w00 + w01;
                rshi += w10 + w11;
                const int olo = (wm * 16 + g) * PS + c0 * 2;
                const int ohi = olo + 8 * PS;
                *(uint32_t*)(sm + SM_W + olo) = pk(w00, w01);
                *(uint32_t*)(sm + SM_W + ohi) = pk(w10, w11);
            }
            rslo += __shfl_xor_sync(0xffffffffu, rslo, 1);
            rslo += __shfl_xor_sync(0xffffffffu, rslo, 2);
            rshi += __shfl_xor_sync(0xffffffffu, rshi, 1);
            rshi += __shfl_xor_sync(0xffffffffu, rshi, 2);
            if (tig == 0) {
                atomicAdd(&sAcc[f * 64 + wm * 16 + g], rslo);
                atomicAdd(&sAcc[f * 64 + wm * 16 + g + 8], rshi);
            }
        }
        __syncthreads();

        // ---- GEMM2: A += W Y  (B via ldmatrix.trans)
#pragma unroll
        for (int ks = 0; ks < 8; ks++) {
            uint32_t aw[4];
            ldsm4(aw, base + SM_W + aBase + ks * 32);
            uint32_t ty[4][4];
#pragma unroll
            for (int p = 0; p < 4; p++)
                ldsm4t(ty[p], yb + tBase + p * 32 + ks * 4352);
#pragma unroll
            for (int nt = 0; nt < 8; nt++) {
                uint32_t* bh = &ty[nt >> 1][(nt & 1) * 2];
                mma16816(accA[nt], aw, bh[0], bh[1]);
            }
        }

        // ---- end of field: dump A partials, reset accumulators
        if (jt == 15) {
            const int rlo = rb * 64 + wm * 16 + g;
            float* dstB = A_scr[f * 2 + strip];
#pragma unroll
            for (int nt = 0; nt < 8; nt++) {
                const int c = wn * 64 + nt * 8 + 2 * tig;
                float* d0 = dstB + (size_t)rlo * 128 + c;
                d0[0] = accA[nt][0];
                d0[1] = accA[nt][1];
                d0[8 * 128] = accA[nt][2];
                d0[8 * 128 + 1] = accA[nt][3];
#pragma unroll
                for (int k = 0; k < 4; k++) accA[nt][k] = 0.f;
            }
        }
    }

    __syncthreads();
    if (tid < 128) {
        int f = tid >> 6, r = tid & 63;
        s_scr[f * 2 + strip][rb * 64 + r] = sAcc[tid];
    }
}

// ---------------- combine ----------------
__global__ void combine_k(const float* __restrict__ x, float* __restrict__ out) {
    const int i = blockIdx.x;      // 4096 rows
    const int d = threadIdx.x;     // 128 features
    float sp = s_scr[0][i] + s_scr[1][i];
    float sn = s_scr[2][i] + s_scr[3][i];
    float Ap = A_scr[0][(size_t)i * 128 + d] + A_scr[1][(size_t)i * 128 + d];
    float An = A_scr[2][(size_t)i * 128 + d] + A_scr[3][(size_t)i * 128 + d];
    float dp = fmaxf(sp, EPSV), dn = fmaxf(sn, EPSV);
    float cx = 0.5f * (sn / dn) - sp / dp;
    out[(size_t)i * 128 + d] = x[(size_t)i * 128 + d] * cx + Ap / dp - 0.5f * An / dn;
}

extern "C" void kernel_launch(void* const* d_in, const int* in_sizes, int n_in,
                              void* d_out, int out_size) {
    const float* x  = (const float*)d_in[0];
    const float* yp = (const float*)d_in[1];
    const float* yn = (const float*)d_in[2];
    float* out = (float*)d_out;

    cudaFuncSetAttribute(drift_main,
                         cudaFuncAttributeMaxDynamicSharedMemorySize, SMEM_TOTAL);

    prep<<<384, 256>>>(x, yp, yn);
    drift_main<<<128, 256, SMEM_TOTAL>>>();
    combine_k<<<4096, 128>>>(x, out);
}

// round 15
// speedup vs baseline: 4.9687x; 1.0767x over previous
#include <cuda_runtime.h>
#include <cuda_bf16.h>
#include <cstdint>

#define EPSV 1e-8f
#define PS 272                 // smem row stride in bytes (136 bf16)

// ---------------- gmem scratch (device globals; no allocs allowed) ----------
__device__ float g_xsq[4096];
__device__ float g_ysq[2][4096];
__device__ __align__(16) uint32_t g_xb[4096 * 64];      // bf16x2 packed
__device__ __align__(16) uint32_t g_yb[2][4096 * 64];
__device__ float A_scr[8][4096 * 128];   // [(f*2+strip)*2+wn][row][d]
__device__ float s_scr[4][4096];         // [f*2+strip][row]

// ---------------- helpers ----------------
__device__ __forceinline__ uint32_t su32(const void* p) {
    return (uint32_t)__cvta_generic_to_shared(p);
}
__device__ __forceinline__ void ldsm4(uint32_t* r, uint32_t a) {
    asm volatile("ldmatrix.sync.aligned.m8n8.x4.shared.b16 {%0,%1,%2,%3},[%4];"
                 : "=r"(r[0]), "=r"(r[1]), "=r"(r[2]), "=r"(r[3]) : "r"(a));
}
__device__ __forceinline__ void ldsm4t(uint32_t* r, uint32_t a) {
    asm volatile("ldmatrix.sync.aligned.m8n8.x4.trans.shared.b16 {%0,%1,%2,%3},[%4];"
                 : "=r"(r[0]), "=r"(r[1]), "=r"(r[2]), "=r"(r[3]) : "r"(a));
}
__device__ __forceinline__ void mma16816(float* c, const uint32_t* a,
                                         uint32_t b0, uint32_t b1) {
    asm volatile(
        "mma.sync.aligned.m16n8k16.row.col.f32.bf16.bf16.f32 "
        "{%0,%1,%2,%3},{%4,%5,%6,%7},{%8,%9},{%0,%1,%2,%3};"
        : "+f"(c[0]), "+f"(c[1]), "+f"(c[2]), "+f"(c[3])
        : "r"(a[0]), "r"(a[1]), "r"(a[2]), "r"(a[3]), "r"(b0), "r"(b1));
}
#define CP16(dst, src) \
    asm volatile("cp.async.cg.shared.global [%0],[%1],16;" :: "r"(dst), "l"(src))
#define CP_COMMIT() asm volatile("cp.async.commit_group;")
#define CP_WAIT1()  asm volatile("cp.async.wait_group 1;")
#define CP_WAIT0()  asm volatile("cp.async.wait_group 0;")

__device__ __forceinline__ uint32_t pk(float a, float b) {
    __nv_bfloat162 h = __floats2bfloat162_rn(a, b);
    return *reinterpret_cast<uint32_t*>(&h);
}

// ---------------- prep: norms + bf16 pack, 16 threads per row --------------
__global__ void prep(const float* __restrict__ x,
                     const float* __restrict__ yp,
                     const float* __restrict__ yn) {
    int idx = blockIdx.x * blockDim.x + threadIdx.x;   // 0 .. 3*4096*16-1
    if (idx >= 3 * 4096 * 16) return;
    int seg = idx & 15;
    int r = idx >> 4;
    int which = r >> 12, row = r & 4095;
    const float* src;
    uint32_t* db;
    float* ds;
    if (which == 0)      { src = x;  db = g_xb;    ds = g_xsq;    }
    else if (which == 1) { src = yp; db = g_yb[0]; ds = g_ysq[0]; }
    else                 { src = yn; db = g_yb[1]; ds = g_ysq[1]; }
    float4 v = *(const float4*)(src + (size_t)row * 128 + seg * 8);
    float4 v2 = *(const float4*)(src + (size_t)row * 128 + seg * 8 + 4);
    uint32_t* ob = db + (size_t)row * 64 + seg * 4;
    float s = v.x * v.x + v.y * v.y + v.z * v.z + v.w * v.w
            + v2.x * v2.x + v2.y * v2.y + v2.z * v2.z + v2.w * v2.w;
    ob[0] = pk(v.x, v.y);
    ob[1] = pk(v.z, v.w);
    ob[2] = pk(v2.x, v2.y);
    ob[3] = pk(v2.z, v2.w);
    s += __shfl_xor_sync(0xffffffffu, s, 1);
    s += __shfl_xor_sync(0xffffffffu, s, 2);
    s += __shfl_xor_sync(0xffffffffu, s, 4);
    s += __shfl_xor_sync(0xffffffffu, s, 8);
    if (seg == 0) ds[row] = s;
}

// ---------------- smem layout (bytes) ----------------
#define SM_X  0                        // 64 x PS   = 17408
#define SM_Y  17408                    // 2 bufs x 128 x PS (stride YBUF)
#define YBUF  34816
#define SM_F  (SM_Y + 2 * YBUF)        // 87040: xsq[64] ysq[2][128] sAcc[2][64]
#define SMEM_TOTAL (SM_F + 1792)

__global__ __launch_bounds__(256, 1)
void drift_main() {
    extern __shared__ char sm[];
    const uint32_t base = su32(sm);
    float* xsqS = (float*)(sm + SM_F);   // [64]
    float* ysqS = xsqS + 64;             // [2][128]
    float* sAcc = ysqS + 256;            // [2][64]

    const int tid = threadIdx.x, lane = tid & 31, w = tid >> 5;
    const int wm = w >> 1, wn = w & 1;
    const int rb = blockIdx.x >> 1, strip = blockIdx.x & 1;
    const int e = lane & 7, q = lane >> 3, g = lane >> 2, tig = lane & 3;

    // per-lane ldmatrix base offsets
    const uint32_t aBase = (uint32_t)((wm * 16 + e + (q & 1) * 8) * PS + (q >> 1) * 16);
    const uint32_t bBase = (uint32_t)((wn * 64 + e + (q >> 1) * 8) * PS + (q & 1) * 16);
    // GEMM2 B (trans): j-rows = wn*64 + ks*16 + e + (q&1)*8, d-cols = dp*16 + (q>>1)*8
    const uint32_t tBase = (uint32_t)((wn * 64 + e + (q & 1) * 8) * PS + ((q >> 1) * 8) * 2);

    // ---- preload X tile + Y tile 0 (one cp.async group)
    {
        const size_t xoff = (size_t)rb * 64 * 64;         // uint32 units
        for (int i = tid; i < 64 * 16; i += 256) {
            int row = i >> 4, ch = i & 15;
            CP16(base + SM_X + row * PS + ch * 16, g_xb + xoff + row * 64 + ch * 4);
        }
        const size_t yoff = (size_t)strip * 2048 * 64;
        for (int i = tid; i < 128 * 16; i += 256) {
            int row = i >> 4, ch = i & 15;
            CP16(base + SM_Y + row * PS + ch * 16, g_yb[0] + yoff + row * 64 + ch * 4);
        }
        CP_COMMIT();
    }
    if (tid < 64)  xsqS[tid] = g_xsq[rb * 64 + tid];
    if (tid < 128) ysqS[tid] = g_ysq[0][strip * 2048 + tid];
    if (tid < 128) sAcc[tid] = 0.f;

    // accA[nt][4]: nt = d-tile (8 cols), k-split: this warp contracts only
    // its own 64 j-columns; partials summed in combine.
    float accA[16][4];
#pragma unroll
    for (int nt = 0; nt < 16; nt++)
#pragma unroll
        for (int k = 0; k < 4; k++) accA[nt][k] = 0.f;

#pragma unroll 1
    for (int t = 0; t < 32; t++) {
        const int f = t >> 4, jt = t & 15, b = t & 1;
        const int jbase = strip * 2048 + jt * 128;

        __syncthreads();   // prev iteration's compute done (buf b^1 free)

        // prefetch next Y tile
        if (t + 1 < 32) {
            const int f2 = (t + 1) >> 4, j2 = (t + 1) & 15, nb = b ^ 1;
            const int jb2 = strip * 2048 + j2 * 128;
            const uint32_t yd = base + SM_Y + nb * YBUF;
            const size_t yoff = (size_t)jb2 * 64;
            for (int i = tid; i < 128 * 16; i += 256) {
                int row = i >> 4, ch = i & 15;
                CP16(yd + row * PS + ch * 16, g_yb[f2] + yoff + row * 64 + ch * 4);
            }
            CP_COMMIT();
            if (tid < 128) ysqS[nb * 128 + tid] = g_ysq[f2][jb2 + tid];
            CP_WAIT1();
        } else {
            CP_WAIT0();
        }
        __syncthreads();

        const uint32_t yb = base + SM_Y + b * YBUF;

        // ---- GEMM1: S = Xb Yb^T  (bf16 x bf16, fp32 accum)
        float S[8][4];
#pragma unroll
        for (int nt = 0; nt < 8; nt++)
#pragma unroll
            for (int k = 0; k < 4; k++) S[nt][k] = 0.f;

#pragma unroll
        for (int ks = 0; ks < 8; ks++) {
            uint32_t ax[4];
            ldsm4(ax, base + SM_X + aBase + ks * 32);
#pragma unroll
            for (int p = 0; p < 4; p++) {
                uint32_t by[4];
                ldsm4(by, yb + bBase + p * 4352 + ks * 32);
                mma16816(S[2 * p], ax, by[0], by[1]);
                mma16816(S[2 * p + 1], ax, by[2], by[3]);
            }
        }

        // ---- epilogue: w = exp(-d2/2), diag mask, row sums,
        //      repack W directly into A-fragments (no smem round-trip)
        uint32_t wpk[4][4];
        {
            const int rlo = rb * 64 + wm * 16 + g, rhi = rlo + 8;
            const float xqlo = xsqS[wm * 16 + g], xqhi = xsqS[wm * 16 + g + 8];
            const float* ys = ysqS + b * 128;
            float rslo = 0.f, rshi = 0.f;
#pragma unroll
            for (int nt = 0; nt < 8; nt++) {
                const int c0 = wn * 64 + nt * 8 + 2 * tig;
                const int gj0 = jbase + c0;
                const float yq0 = ys[c0], yq1 = ys[c0 + 1];
                float w00 = (rlo == gj0) ? 0.f
                    : __expf(-0.5f * fmaxf(xqlo + yq0 - 2.f * S[nt][0], 0.f));
                float w01 = (rlo == gj0 + 1) ? 0.f
                    : __expf(-0.5f * fmaxf(xqlo + yq1 - 2.f * S[nt][1], 0.f));
                float w10 = (rhi == gj0) ? 0.f
                    : __expf(-0.5f * fmaxf(xqhi + yq0 - 2.f * S[nt][2], 0.f));
                float w11 = (rhi == gj0 + 1) ? 0.f
                    : __expf(-0.5f * fmaxf(xqhi + yq1 - 2.f * S[nt][3], 0.f));
                rslo += w00 + w01;
                rshi += w10 + w11;
                // A-fragment for k-slice ks = nt>>1: regs {a0,a1} from even nt,
                // {a2,a3} from odd nt
                wpk[nt >> 1][(nt & 1) * 2]     = pk(w00, w01);
                wpk[nt >> 1][(nt & 1) * 2 + 1] = pk(w10, w11);
            }
            rslo += __shfl_xor_sync(0xffffffffu, rslo, 1);
            rslo += __shfl_xor_sync(0xffffffffu, rslo, 2);
            rshi += __shfl_xor_sync(0xffffffffu, rshi, 1);
            rshi += __shfl_xor_sync(0xffffffffu, rshi, 2);
            if (tig == 0) {
                atomicAdd(&sAcc[f * 64 + wm * 16 + g], rslo);
                atomicAdd(&sAcc[f * 64 + wm * 16 + g + 8], rshi);
            }
        }
        // NO syncthreads: GEMM2 uses only this warp's registers + Y buf b

        // ---- GEMM2: A += W Y over this warp's 64 j's (B via ldmatrix.trans)
#pragma unroll
        for (int ks = 0; ks < 4; ks++) {
#pragma unroll
            for (int dp = 0; dp < 8; dp++) {
                uint32_t ty[4];
                ldsm4t(ty, yb + tBase + ks * (16 * PS) + dp * 32);
                mma16816(accA[2 * dp], wpk[ks], ty[0], ty[1]);
                mma16816(accA[2 * dp + 1], wpk[ks], ty[2], ty[3]);
            }
        }

        // ---- end of field: dump A partials (per-warp disjoint), reset
        if (jt == 15) {
            const int rlo = rb * 64 + wm * 16 + g;
            float* dstB = A_scr[(f * 2 + strip) * 2 + wn];
#pragma unroll
            for (int nt = 0; nt < 16; nt++) {
                const int c = nt * 8 + 2 * tig;
                float* d0 = dstB + (size_t)rlo * 128 + c;
                *(float2*)d0 = make_float2(accA[nt][0], accA[nt][1]);
                *(float2*)(d0 + 8 * 128) = make_float2(accA[nt][2], accA[nt][3]);
#pragma unroll
                for (int k = 0; k < 4; k++) accA[nt][k] = 0.f;
            }
        }
    }

    __syncthreads();
    if (tid < 128) {
        int f = tid >> 6, r = tid & 63;
        s_scr[f * 2 + strip][rb * 64 + r] = sAcc[tid];
    }
}

// ---------------- combine ----------------
__global__ void combine_k(const float* __restrict__ x, float* __restrict__ out) {
    const int i = blockIdx.x;      // 4096 rows
    const int d = threadIdx.x;     // 128 features
    float sp = s_scr[0][i] + s_scr[1][i];
    float sn = s_scr[2][i] + s_scr[3][i];
    const size_t o = (size_t)i * 128 + d;
    float Ap = A_scr[0][o] + A_scr[1][o] + A_scr[2][o] + A_scr[3][o];
    float An = A_scr[4][o] + A_scr[5][o] + A_scr[6][o] + A_scr[7][o];
    float dp = fmaxf(sp, EPSV), dn = fmaxf(sn, EPSV);
    float cx = 0.5f * (sn / dn) - sp / dp;
    out[o] = x[o] * cx + Ap / dp - 0.5f * An / dn;
}

extern "C" void kernel_launch(void* const* d_in, const int* in_sizes, int n_in,
                              void* d_out, int out_size) {
    const float* x  = (const float*)d_in[0];
    const float* yp = (const float*)d_in[1];
    const float* yn = (const float*)d_in[2];
    float* out = (float*)d_out;

    cudaFuncSetAttribute(drift_main,
                         cudaFuncAttributeMaxDynamicSharedMemorySize, SMEM_TOTAL);

    prep<<<768, 256>>>(x, yp, yn);
    drift_main<<<128, 256, SMEM_TOTAL>>>();
    combine_k<<<4096, 128>>>(x, out);
}

// round 17
// speedup vs baseline: 5.4121x; 1.0892x over previous
#include <cuda_runtime.h>
#include <cuda_bf16.h>
#include <cstdint>

#define EPSV 1e-8f
#define PS 272                 // smem row stride in bytes (136 bf16)
#define NT 512

// ---------------- gmem scratch (device globals; no allocs allowed) ----------
__device__ float g_xsq[4096];
__device__ float g_ysq[2][4096];
__device__ __align__(16) uint32_t g_xb[4096 * 64];      // bf16x2 packed
__device__ __align__(16) uint32_t g_yb[2][4096 * 64];
__device__ float A_scr[16][4096 * 128];  // [(f*2+strip)*4+wn][row][d]
__device__ float s_scr[4][4096];         // [f*2+strip][row]

// ---------------- helpers ----------------
__device__ __forceinline__ uint32_t su32(const void* p) {
    return (uint32_t)__cvta_generic_to_shared(p);
}
__device__ __forceinline__ void ldsm4(uint32_t* r, uint32_t a) {
    asm volatile("ldmatrix.sync.aligned.m8n8.x4.shared.b16 {%0,%1,%2,%3},[%4];"
                 : "=r"(r[0]), "=r"(r[1]), "=r"(r[2]), "=r"(r[3]) : "r"(a));
}
__device__ __forceinline__ void ldsm4t(uint32_t* r, uint32_t a) {
    asm volatile("ldmatrix.sync.aligned.m8n8.x4.trans.shared.b16 {%0,%1,%2,%3},[%4];"
                 : "=r"(r[0]), "=r"(r[1]), "=r"(r[2]), "=r"(r[3]) : "r"(a));
}
__device__ __forceinline__ void mma16816(float* c, const uint32_t* a,
                                         uint32_t b0, uint32_t b1) {
    asm volatile(
        "mma.sync.aligned.m16n8k16.row.col.f32.bf16.bf16.f32 "
        "{%0,%1,%2,%3},{%4,%5,%6,%7},{%8,%9},{%0,%1,%2,%3};"
        : "+f"(c[0]), "+f"(c[1]), "+f"(c[2]), "+f"(c[3])
        : "r"(a[0]), "r"(a[1]), "r"(a[2]), "r"(a[3]), "r"(b0), "r"(b1));
}
#define CP16(dst, src) \
    asm volatile("cp.async.cg.shared.global [%0],[%1],16;" :: "r"(dst), "l"(src))
#define CP_COMMIT() asm volatile("cp.async.commit_group;")
#define CP_WAIT1()  asm volatile("cp.async.wait_group 1;")
#define CP_WAIT0()  asm volatile("cp.async.wait_group 0;")

__device__ __forceinline__ uint32_t pk(float a, float b) {
    __nv_bfloat162 h = __floats2bfloat162_rn(a, b);
    return *reinterpret_cast<uint32_t*>(&h);
}

// ---------------- prep: norms + bf16 pack, 16 threads per row --------------
__global__ void prep(const float* __restrict__ x,
                     const float* __restrict__ yp,
                     const float* __restrict__ yn) {
    int idx = blockIdx.x * blockDim.x + threadIdx.x;   // 0 .. 3*4096*16-1
    if (idx >= 3 * 4096 * 16) return;
    int seg = idx & 15;
    int r = idx >> 4;
    int which = r >> 12, row = r & 4095;
    const float* src;
    uint32_t* db;
    float* ds;
    if (which == 0)      { src = x;  db = g_xb;    ds = g_xsq;    }
    else if (which == 1) { src = yp; db = g_yb[0]; ds = g_ysq[0]; }
    else                 { src = yn; db = g_yb[1]; ds = g_ysq[1]; }
    float4 v = *(const float4*)(src + (size_t)row * 128 + seg * 8);
    float4 v2 = *(const float4*)(src + (size_t)row * 128 + seg * 8 + 4);
    uint32_t* ob = db + (size_t)row * 64 + seg * 4;
    float s = v.x * v.x + v.y * v.y + v.z * v.z + v.w * v.w
            + v2.x * v2.x + v2.y * v2.y + v2.z * v2.z + v2.w * v2.w;
    ob[0] = pk(v.x, v.y);
    ob[1] = pk(v.z, v.w);
    ob[2] = pk(v2.x, v2.y);
    ob[3] = pk(v2.z, v2.w);
    s += __shfl_xor_sync(0xffffffffu, s, 1);
    s += __shfl_xor_sync(0xffffffffu, s, 2);
    s += __shfl_xor_sync(0xffffffffu, s, 4);
    s += __shfl_xor_sync(0xffffffffu, s, 8);
    if (seg == 0) ds[row] = s;
}

// ---------------- smem layout (bytes) ----------------
#define SM_X  0                        // 64 x PS   = 17408
#define SM_Y  17408                    // 2 bufs x 128 x PS (stride YBUF)
#define YBUF  34816
#define SM_F  (SM_Y + 2 * YBUF)        // 87040: xsq[64] ysq[2][128] sAcc[2][64]
#define SMEM_TOTAL (SM_F + 1792)

__global__ __launch_bounds__(NT, 1)
void drift_main() {
    extern __shared__ char sm[];
    const uint32_t base = su32(sm);
    float* xsqS = (float*)(sm + SM_F);   // [64]
    float* ysqS = xsqS + 64;             // [2][128]
    float* sAcc = ysqS + 256;            // [2][64]

    const int tid = threadIdx.x, lane = tid & 31, w = tid >> 5;
    const int wm = w >> 2, wn = w & 3;           // 4 x 4 warp grid
    const int rb = blockIdx.x >> 1, strip = blockIdx.x & 1;
    const int e = lane & 7, q = lane >> 3, g = lane >> 2, tig = lane & 3;

    // per-lane ldmatrix base offsets
    const uint32_t aBase = (uint32_t)((wm * 16 + e + (q & 1) * 8) * PS + (q >> 1) * 16);
    const uint32_t bBase = (uint32_t)((wn * 32 + e + (q >> 1) * 8) * PS + (q & 1) * 16);
    // GEMM2 B (trans): j-rows = wn*32 + ks*16 + e + (q&1)*8, d-cols = dp*16 + (q>>1)*8
    const uint32_t tBase = (uint32_t)((wn * 32 + e + (q & 1) * 8) * PS + ((q >> 1) * 8) * 2);

    // ---- preload X tile + Y tile 0 (one cp.async group)
    {
        const size_t xoff = (size_t)rb * 64 * 64;         // uint32 units
        for (int i = tid; i < 64 * 16; i += NT) {
            int row = i >> 4, ch = i & 15;
            CP16(base + SM_X + row * PS + ch * 16, g_xb + xoff + row * 64 + ch * 4);
        }
        const size_t yoff = (size_t)strip * 2048 * 64;
        for (int i = tid; i < 128 * 16; i += NT) {
            int row = i >> 4, ch = i & 15;
            CP16(base + SM_Y + row * PS + ch * 16, g_yb[0] + yoff + row * 64 + ch * 4);
        }
        CP_COMMIT();
    }
    if (tid < 64)  xsqS[tid] = g_xsq[rb * 64 + tid];
    if (tid < 128) ysqS[tid] = g_ysq[0][strip * 2048 + tid];
    if (tid < 128) sAcc[tid] = 0.f;

    // accA[nt][4]: nt = d-tile (8 cols); this warp contracts only its own
    // 32 j-columns; partials summed in combine.
    float accA[16][4];
#pragma unroll
    for (int nt = 0; nt < 16; nt++)
#pragma unroll
        for (int k = 0; k < 4; k++) accA[nt][k] = 0.f;

#pragma unroll 1
    for (int t = 0; t < 32; t++) {
        const int f = t >> 4, jt = t & 15, b = t & 1;
        const int jbase = strip * 2048 + jt * 128;

        __syncthreads();   // prev iteration's compute done (buf b^1 free)

        // prefetch next Y tile
        if (t + 1 < 32) {
            const int f2 = (t + 1) >> 4, j2 = (t + 1) & 15, nb = b ^ 1;
            const int jb2 = strip * 2048 + j2 * 128;
            const uint32_t yd = base + SM_Y + nb * YBUF;
            const size_t yoff = (size_t)jb2 * 64;
            for (int i = tid; i < 128 * 16; i += NT) {
                int row = i >> 4, ch = i & 15;
                CP16(yd + row * PS + ch * 16, g_yb[f2] + yoff + row * 64 + ch * 4);
            }
            CP_COMMIT();
            if (tid < 128) ysqS[nb * 128 + tid] = g_ysq[f2][jb2 + tid];
            CP_WAIT1();
        } else {
            CP_WAIT0();
        }
        __syncthreads();

        const uint32_t yb = base + SM_Y + b * YBUF;

        // ---- GEMM1: S = Xb Yb^T  (m16 x n32 per warp)
        float S[4][4];
#pragma unroll
        for (int nt = 0; nt < 4; nt++)
#pragma unroll
            for (int k = 0; k < 4; k++) S[nt][k] = 0.f;

#pragma unroll
        for (int ks = 0; ks < 8; ks++) {
            uint32_t ax[4];
            ldsm4(ax, base + SM_X + aBase + ks * 32);
#pragma unroll
            for (int p = 0; p < 2; p++) {
                uint32_t by[4];
                ldsm4(by, yb + bBase + p * 4352 + ks * 32);
                mma16816(S[2 * p], ax, by[0], by[1]);
                mma16816(S[2 * p + 1], ax, by[2], by[3]);
            }
        }

        // ---- epilogue: w = exp(-d2/2), diag mask, row sums,
        //      repack W directly into A-fragments (no smem round-trip)
        uint32_t wpk[2][4];
        {
            const int rlo = rb * 64 + wm * 16 + g, rhi = rlo + 8;
            const float xqlo = xsqS[wm * 16 + g], xqhi = xsqS[wm * 16 + g + 8];
            const float* ys = ysqS + b * 128;
            float rslo = 0.f, rshi = 0.f;
#pragma unroll
            for (int nt = 0; nt < 4; nt++) {
                const int c0 = wn * 32 + nt * 8 + 2 * tig;
                const int gj0 = jbase + c0;
                const float yq0 = ys[c0], yq1 = ys[c0 + 1];
                float w00 = (rlo == gj0) ? 0.f
                    : __expf(-0.5f * fmaxf(xqlo + yq0 - 2.f * S[nt][0], 0.f));
                float w01 = (rlo == gj0 + 1) ? 0.f
                    : __expf(-0.5f * fmaxf(xqlo + yq1 - 2.f * S[nt][1], 0.f));
                float w10 = (rhi == gj0) ? 0.f
                    : __expf(-0.5f * fmaxf(xqhi + yq0 - 2.f * S[nt][2], 0.f));
                float w11 = (rhi == gj0 + 1) ? 0.f
                    : __expf(-0.5f * fmaxf(xqhi + yq1 - 2.f * S[nt][3], 0.f));
                rslo += w00 + w01;
                rshi += w10 + w11;
                wpk[nt >> 1][(nt & 1) * 2]     = pk(w00, w01);
                wpk[nt >> 1][(nt & 1) * 2 + 1] = pk(w10, w11);
            }
            rslo += __shfl_xor_sync(0xffffffffu, rslo, 1);
            rslo += __shfl_xor_sync(0xffffffffu, rslo, 2);
            rshi += __shfl_xor_sync(0xffffffffu, rshi, 1);
            rshi += __shfl_xor_sync(0xffffffffu, rshi, 2);
            if (tig == 0) {
                atomicAdd(&sAcc[f * 64 + wm * 16 + g], rslo);
                atomicAdd(&sAcc[f * 64 + wm * 16 + g + 8], rshi);
            }
        }
        // NO syncthreads: GEMM2 uses only this warp's registers + Y buf b

        // ---- GEMM2: A += W Y over this warp's 32 j's (B via ldmatrix.trans)
#pragma unroll
        for (int ks = 0; ks < 2; ks++) {
#pragma unroll
            for (int dp = 0; dp < 8; dp++) {
                uint32_t ty[4];
                ldsm4t(ty, yb + tBase + ks * (16 * PS) + dp * 32);
                mma16816(accA[2 * dp], wpk[ks], ty[0], ty[1]);
                mma16816(accA[2 * dp + 1], wpk[ks], ty[2], ty[3]);
            }
        }

        // ---- end of field: dump A partials (per-warp disjoint), reset
        if (jt == 15) {
            const int rlo = rb * 64 + wm * 16 + g;
            float* dstB = A_scr[(f * 2 + strip) * 4 + wn];
#pragma unroll
            for (int nt = 0; nt < 16; nt++) {
                const int c = nt * 8 + 2 * tig;
                float* d0 = dstB + (size_t)rlo * 128 + c;
                *(float2*)d0 = make_float2(accA[nt][0], accA[nt][1]);
                *(float2*)(d0 + 8 * 128) = make_float2(accA[nt][2], accA[nt][3]);
#pragma unroll
                for (int k = 0; k < 4; k++) accA[nt][k] = 0.f;
            }
        }
    }

    __syncthreads();
    if (tid < 128) {
        int f = tid >> 6, r = tid & 63;
        s_scr[f * 2 + strip][rb * 64 + r] = sAcc[tid];
    }
}

// ---------------- combine ----------------
__global__ void combine_k(const float* __restrict__ x, float* __restrict__ out) {
    const int i = blockIdx.x;      // 4096 rows
    const int d = threadIdx.x;     // 128 features
    float sp = s_scr[0][i] + s_scr[1][i];
    float sn = s_scr[2][i] + s_scr[3][i];
    const size_t o = (size_t)i * 128 + d;
    float Ap = 0.f, An = 0.f;
#pragma unroll
    for (int k = 0; k < 8; k++) {
        Ap += A_scr[k][o];
        An += A_scr[8 + k][o];
    }
    float dp = fmaxf(sp, EPSV), dn = fmaxf(sn, EPSV);
    float cx = 0.5f * (sn / dn) - sp / dp;
    out[o] = x[o] * cx + Ap / dp - 0.5f * An / dn;
}

extern "C" void kernel_launch(void* const* d_in, const int* in_sizes, int n_in,
                              void* d_out, int out_size) {
    const float* x  = (const float*)d_in[0];
    const float* yp = (const float*)d_in[1];
    const float* yn = (const float*)d_in[2];
    float* out = (float*)d_out;

    cudaFuncSetAttribute(drift_main,
                         cudaFuncAttributeMaxDynamicSharedMemorySize, SMEM_TOTAL);

    prep<<<768, 256>>>(x, yp, yn);
    drift_main<<<128, NT, SMEM_TOTAL>>>();
    combine_k<<<4096, 128>>>(x, out);
}